// round 2
// baseline (speedup 1.0000x reference)
#include <cuda_runtime.h>
#include <math.h>

#define MAXL 12288
#define SPLITS 16
#define K1_THREADS 256
#define K2_THREADS 256
#define MAXBLK 256

// scratch: partial sums per row-split: [split][b(0..7)=acc, 8=count][column]
__device__ float g_part[SPLITS][9][MAXL];
// per-block partial squared-diff sums from k2
__device__ float g_bsum[MAXBLK][8];

// ---------------------------------------------------------------------------
// k1: masked column-wise accumulation. Mask is FLOAT32 (0.0/1.0).
// thread -> column j; blockIdx.y -> row split. Mask loads coalesced (128B/warp).
// adj loaded ONLY where mask != 0 (1% density -> ~7.7% of sectors touched).
// ---------------------------------------------------------------------------
__global__ void __launch_bounds__(K1_THREADS)
k1_masked_gemv(const float* __restrict__ predicts,
               const float* __restrict__ adj,
               const float* __restrict__ mask,
               int L)
{
    int j = blockIdx.x * K1_THREADS + threadIdx.x;
    if (j >= L) return;
    int s = blockIdx.y;
    int rows = L / SPLITS;              // 768, divisible by 8
    int i0 = s * rows;
    int i1 = i0 + rows;

    float acc0=0.f,acc1=0.f,acc2=0.f,acc3=0.f,acc4=0.f,acc5=0.f,acc6=0.f,acc7=0.f;
    float cnt = 0.f;

    for (int i = i0; i < i1; i += 8) {
        // front-batch 8 independent mask loads for MLP
        float m[8];
        #pragma unroll
        for (int u = 0; u < 8; u++)
            m[u] = mask[(long long)(i+u)*L + j];

        float any = m[0]+m[1]+m[2]+m[3]+m[4]+m[5]+m[6]+m[7];
        if (any != 0.f) {
            #pragma unroll
            for (int u = 0; u < 8; u++) {
                if (m[u] != 0.f) {
                    int ii = i + u;
                    float a = __ldg(&adj[(long long)ii*L + j]);
                    acc0 = fmaf(__ldg(&predicts[0*L + ii]), a, acc0);
                    acc1 = fmaf(__ldg(&predicts[1*L + ii]), a, acc1);
                    acc2 = fmaf(__ldg(&predicts[2*L + ii]), a, acc2);
                    acc3 = fmaf(__ldg(&predicts[3*L + ii]), a, acc3);
                    acc4 = fmaf(__ldg(&predicts[4*L + ii]), a, acc4);
                    acc5 = fmaf(__ldg(&predicts[5*L + ii]), a, acc5);
                    acc6 = fmaf(__ldg(&predicts[6*L + ii]), a, acc6);
                    acc7 = fmaf(__ldg(&predicts[7*L + ii]), a, acc7);
                    cnt += 1.f;
                }
            }
        }
    }

    g_part[s][0][j] = acc0;  g_part[s][1][j] = acc1;
    g_part[s][2][j] = acc2;  g_part[s][3][j] = acc3;
    g_part[s][4][j] = acc4;  g_part[s][5][j] = acc5;
    g_part[s][6][j] = acc6;  g_part[s][7][j] = acc7;
    g_part[s][8][j] = cnt;
}

// ---------------------------------------------------------------------------
// k2: per-column epilogue. Reduce splits, add identity term, divide by counts,
// diff = p - sim @ cand, block-reduce the 8 per-batch squared sums.
// ---------------------------------------------------------------------------
__global__ void __launch_bounds__(K2_THREADS)
k2_epilogue(const float* __restrict__ predicts,
            const float* __restrict__ sim,
            const float* __restrict__ mask,
            int L)
{
    __shared__ float s_sim[64];
    __shared__ float s_red[K2_THREADS / 32][8];

    int tid = threadIdx.x;
    if (tid < 64) s_sim[tid] = sim[tid];
    __syncthreads();

    int j = blockIdx.x * K2_THREADS + tid;
    float sq[8];
    #pragma unroll
    for (int b = 0; b < 8; b++) sq[b] = 0.f;

    if (j < L) {
        float acc[9];
        #pragma unroll
        for (int b = 0; b < 9; b++) acc[b] = 0.f;
        #pragma unroll
        for (int s = 0; s < SPLITS; s++) {
            #pragma unroll
            for (int b = 0; b < 9; b++) acc[b] += g_part[s][b][j];
        }
        float mjj   = mask[(long long)j*L + j];
        float extra = 1.f - mjj;
        float inv_c = 1.f / (acc[8] + extra);   // counts[j] >= 1 always

        float p[8], cand[8];
        #pragma unroll
        for (int b = 0; b < 8; b++) {
            p[b]    = predicts[b*L + j];
            cand[b] = (acc[b] + p[b] * extra) * inv_c;
        }
        #pragma unroll
        for (int b = 0; b < 8; b++) {
            float d = p[b];
            #pragma unroll
            for (int bb = 0; bb < 8; bb++)
                d = fmaf(-s_sim[b*8 + bb], cand[bb], d);
            sq[b] = d * d;
        }
    }

    // block reduction of 8 partial sums
    int lane = tid & 31, warp = tid >> 5;
    #pragma unroll
    for (int b = 0; b < 8; b++) {
        float v = sq[b];
        #pragma unroll
        for (int off = 16; off > 0; off >>= 1)
            v += __shfl_xor_sync(0xFFFFFFFFu, v, off);
        if (lane == 0) s_red[warp][b] = v;
    }
    __syncthreads();
    if (warp == 0) {
        #pragma unroll
        for (int b = 0; b < 8; b++) {
            float v = (lane < K2_THREADS/32) ? s_red[lane][b] : 0.f;
            #pragma unroll
            for (int off = 4; off > 0; off >>= 1)
                v += __shfl_xor_sync(0xFFFFFFFFu, v, off);
            if (lane == 0) g_bsum[blockIdx.x][b] = v;
        }
    }
}

// ---------------------------------------------------------------------------
// k3: final scalar. norms = sqrt(sumsq[b]); valid = rowsum(sim) != 0.
// ---------------------------------------------------------------------------
__global__ void k3_final(const float* __restrict__ sim,
                         float* __restrict__ out,
                         int nblocks)
{
    if (threadIdx.x != 0 || blockIdx.x != 0) return;
    float total = 0.f, cnt = 0.f;
    for (int b = 0; b < 8; b++) {
        float ss = 0.f;
        for (int k = 0; k < nblocks; k++) ss += g_bsum[k][b];
        float rs = 0.f;
        for (int bb = 0; bb < 8; bb++) rs += sim[b*8 + bb];
        if (rs != 0.f) {
            total += sqrtf(ss);
            cnt   += 1.f;
        }
    }
    out[0] = (cnt == 0.f) ? 0.f : total / fmaxf(cnt, 1.f);
}

// ---------------------------------------------------------------------------
extern "C" void kernel_launch(void* const* d_in, const int* in_sizes, int n_in,
                              void* d_out, int out_size)
{
    const float* predicts = (const float*)d_in[0];
    const float* sim      = (const float*)d_in[1];
    const float* adj      = (const float*)d_in[2];
    const float* mask     = (const float*)d_in[3];
    float*       out      = (float*)d_out;

    const int B = 8;
    const int L = in_sizes[0] / B;        // 12288

    int colblocks = (L + K1_THREADS - 1) / K1_THREADS;   // 48
    dim3 g1(colblocks, SPLITS);
    k1_masked_gemv<<<g1, K1_THREADS>>>(predicts, adj, mask, L);

    int k2blocks = (L + K2_THREADS - 1) / K2_THREADS;    // 48
    k2_epilogue<<<k2blocks, K2_THREADS>>>(predicts, sim, mask, L);

    k3_final<<<1, 32>>>(sim, out, k2blocks);
}